// round 12
// baseline (speedup 1.0000x reference)
#include <cuda_runtime.h>
#include <stdint.h>

// diag(A) @ B : out[i][j] = A[i] * B[i][j]
// N = 8192 rows, M = 8192 cols, fp32. Pure HBM-streaming kernel.
//
// FINAL (confirmed over 10 measured rounds; re-benched twice, stable):
//   - one block == one row: 512 threads x 4 float4 = 8192 floats = M
//   - loads front-batched (4 independent LDG.128 in flight, MLP_p1=4)
//   - .cs (evict-first) on BOTH loads and stores — measured best policy
//     (beats .wb stores, .wt stores, .cg loads, default loads)
//   - flat 8192-block grid; HW CTA scheduler overlaps waves
//     (persistent single-wave grid measured WORSE: 86.5us)
//   - 26 regs, no smem, occ ~76%
// Measured: 73.5-74.4us kernel, DRAM 81.6-82.6% (6465-6544 GB/s).
// This is the HBM read+write turnaround ceiling for a balanced 512MB
// stream; all compute pipes <6%. No remaining lever: cache-policy matrix,
// access width (128/256-bit), MLP depth, occupancy, CTA granularity, and
// persistent scheduling all explored and non-binding or worse.

#define THREADS 512
#define UNROLL  4   // 512 * 4 * 4 floats = 8192 = M (one row per block)

__global__ void __launch_bounds__(THREADS) diag_scale_row512(
    const float* __restrict__ A,
    const float4* __restrict__ B4,
    float4* __restrict__ out4)
{
    const int row = blockIdx.x;                 // 8192 blocks = 8192 rows
    const float a = __ldg(&A[row]);

    const long long base = (long long)row * (THREADS * UNROLL) + threadIdx.x;

    // Front-batch all loads: 4 independent LDG.128 in flight per thread.
    float4 b[UNROLL];
#pragma unroll
    for (int k = 0; k < UNROLL; k++) {
        b[k] = __ldcs(&B4[base + (long long)k * THREADS]);
    }

#pragma unroll
    for (int k = 0; k < UNROLL; k++) {
        float4 o;
        o.x = a * b[k].x;
        o.y = a * b[k].y;
        o.z = a * b[k].z;
        o.w = a * b[k].w;
        __stcs(&out4[base + (long long)k * THREADS], o);
    }
}

extern "C" void kernel_launch(void* const* d_in, const int* in_sizes, int n_in,
                              void* d_out, int out_size)
{
    const float* A = (const float*)d_in[0];
    const float4* B4 = (const float4*)d_in[1];
    float4* out4 = (float4*)d_out;

    int n_rows = (int)((long long)out_size / 8192);  // 8192

    diag_scale_row512<<<n_rows, THREADS>>>(A, B4, out4);
}

// round 13
// speedup vs baseline: 1.0043x; 1.0043x over previous
#include <cuda_runtime.h>
#include <stdint.h>

// diag(A) @ B : out[i][j] = A[i] * B[i][j]
// N = 8192 rows, M = 8192 cols, fp32. Pure HBM-streaming kernel.
//
// FINAL — converged after 11 measured rounds (3 re-benches of this config:
// kernel 73.5/74.4/75.1us, wall 81.9-82.2us; all deltas within noise).
//
//   - one block == one row: 512 threads x 4 float4 = 8192 floats = M
//   - loads front-batched (4 independent LDG.128 in flight, MLP_p1=4)
//   - .cs (evict-first) on BOTH loads and stores — measured best policy
//     (beats .wb stores, .wt stores, .cg loads, default loads)
//   - flat 8192-block grid (persistent single-wave grid measured WORSE)
//   - 26 regs, no smem
//
// Roofline verdict: DRAM 81-83% (6.4-6.55 TB/s) with all compute pipes <6%
// and L2/L1 <43% — pinned at the HBM3e balanced read+write turnaround
// ceiling. Exhausted levers (all neutral or worse): full cache-policy
// matrix, 256-bit LDG/STG, MLP depth 2-8, occupancy 59-87%, CTA granularity
// 1184-16384 blocks, persistent scheduling. Traffic (512 MB) is irreducible.

#define THREADS 512
#define UNROLL  4   // 512 * 4 * 4 floats = 8192 = M (one row per block)

__global__ void __launch_bounds__(THREADS) diag_scale_row512(
    const float* __restrict__ A,
    const float4* __restrict__ B4,
    float4* __restrict__ out4)
{
    const int row = blockIdx.x;                 // 8192 blocks = 8192 rows
    const float a = __ldg(&A[row]);

    const long long base = (long long)row * (THREADS * UNROLL) + threadIdx.x;

    // Front-batch all loads: 4 independent LDG.128 in flight per thread.
    float4 b[UNROLL];
#pragma unroll
    for (int k = 0; k < UNROLL; k++) {
        b[k] = __ldcs(&B4[base + (long long)k * THREADS]);
    }

#pragma unroll
    for (int k = 0; k < UNROLL; k++) {
        float4 o;
        o.x = a * b[k].x;
        o.y = a * b[k].y;
        o.z = a * b[k].z;
        o.w = a * b[k].w;
        __stcs(&out4[base + (long long)k * THREADS], o);
    }
}

extern "C" void kernel_launch(void* const* d_in, const int* in_sizes, int n_in,
                              void* d_out, int out_size)
{
    const float* A = (const float*)d_in[0];
    const float4* B4 = (const float4*)d_in[1];
    float4* out4 = (float4*)d_out;

    int n_rows = (int)((long long)out_size / 8192);  // 8192

    diag_scale_row512<<<n_rows, THREADS>>>(A, B4, out4);
}